// round 12
// baseline (speedup 1.0000x reference)
#include <cuda_runtime.h>
#include <cuda_fp16.h>
#include <cstdint>
#include <math.h>

// ---------------------------------------------------------------------------
// TokenPacker R12: persistent-CTA GEMM (296 CTAs, 2/SM) with the 3-stage
// cp.async pipeline ROLLING across tile boundaries (prefetch of tile t+1
// starts during tile t's last slabs; prologue/drain paid once per CTA, not
// once per tile). Core stage machinery identical to R11 (K=64 slabs,
// sector-clean fill, chunk double-buffer, fp16 m16n8k16, 128x128 tiles).
// ---------------------------------------------------------------------------

#define E_DIM   1024
#define N_IMG   64
#define NQ_TOK  144
#define TN_TOK  576
#define M_BIG   (N_IMG * TN_TOK)   // 36864
#define M_SMALL (N_IMG * NQ_TOK)   // 9216
#define NST     16                 // K-slabs per tile (K=64 each)
#define STAGES  3
#define SROW_B  144                // pitch bytes (128B payload + 16 pad)
#define BM      128
#define BN      128
#define STAGE_B ((BM + BN) * SROW_B)   // 36864
#define PGRID   296                // persistent grid: 2 CTAs x 148 SMs

// Scratch (device statics; no cudaMalloc allowed)
__device__ __align__(256) __half g_h2 [(size_t)M_BIG * 2048];   // gelu(K1|V1)
__device__ __align__(256) __half g_key[(size_t)M_BIG   * E_DIM];
__device__ __align__(256) __half g_val[(size_t)M_BIG   * E_DIM];
__device__ __align__(256) __half g_kh [(size_t)M_BIG   * E_DIM];
__device__ __align__(256) __half g_vh [(size_t)M_BIG   * E_DIM];
__device__ __align__(256) __half g_q  [(size_t)M_SMALL * E_DIM];
__device__ __align__(256) __half g_qh [(size_t)M_SMALL * E_DIM];
__device__ __align__(256) __half g_o  [(size_t)M_SMALL * E_DIM];
__device__ __align__(256) __half g_xr [(size_t)M_SMALL * E_DIM];
__device__ __align__(256) __half g_xfr[(size_t)M_BIG   * E_DIM];
__device__ __align__(256) __half g_wt [9ull * 1024 * 1024];
__device__ __align__(256) float  g_bcat[2048];

__device__ __forceinline__ float gelu_exact(float x) {
    return 0.5f * x * (1.0f + erff(x * 0.70710678118654752f));
}

#define CP_ASYNC16(smem_u32a, gptr) \
    asm volatile("cp.async.cg.shared.global [%0], [%1], 16;\n" :: "r"(smem_u32a), "l"(gptr))

#define LDSM_X4(r0, r1, r2, r3, addr) \
    asm volatile("ldmatrix.sync.aligned.m8n8.x4.shared.b16 {%0,%1,%2,%3}, [%4];" \
                 : "=r"(r0), "=r"(r1), "=r"(r2), "=r"(r3) : "r"(addr))

#define MMA16816(d, a, b) \
    asm volatile("mma.sync.aligned.m16n8k16.row.col.f32.f16.f16.f32 " \
                 "{%0,%1,%2,%3}, {%4,%5,%6,%7}, {%8,%9}, {%0,%1,%2,%3};\n" \
                 : "+f"((d)[0]), "+f"((d)[1]), "+f"((d)[2]), "+f"((d)[3]) \
                 : "r"((a)[0]), "r"((a)[1]), "r"((a)[2]), "r"((a)[3]), \
                   "r"((b)[0]), "r"((b)[1]))

// ---------------------------------------------------------------------------
// Merged f32 -> f16 conversion prepass
// ---------------------------------------------------------------------------
struct ConvJob { const float4* src; __half2* dst; int n4; };
struct ConvJobs { ConvJob j[9]; };

__global__ void conv_all_kernel(ConvJobs jobs)
{
    const ConvJob jb = jobs.j[blockIdx.y];
    for (int i = blockIdx.x * blockDim.x + threadIdx.x; i < jb.n4;
         i += gridDim.x * blockDim.x) {
        float4 v = jb.src[i];
        jb.dst[2 * i]     = __floats2half2_rn(v.x, v.y);
        jb.dst[2 * i + 1] = __floats2half2_rn(v.z, v.w);
    }
}

__global__ void bias_concat_kernel(const float* __restrict__ b0,
                                   const float* __restrict__ b1,
                                   float* __restrict__ out)
{
    int i = blockIdx.x * blockDim.x + threadIdx.x;
    out[i] = (i < 1024) ? b0[i] : b1[i - 1024];
}

// ---------------------------------------------------------------------------
// Persistent GEMM: C[M x N] = act(A[M x K=1024] @ W[N x 1024]^T + bias)
// Tiles enumerated flat: tile t -> col = (t & (nx-1))*128, row = (t >> lognx)*128.
// Each CTA processes tiles bx, bx+G, bx+2G, ... with a rolling pipeline.
// ---------------------------------------------------------------------------
template <int ACT, int OUTF>
__global__ __launch_bounds__(256, 2)
void gemm_f16(const __half* __restrict__ A, int lda,
              const __half* __restrict__ W,
              const float* __restrict__ bias,
              void* __restrict__ Cv, int ldc,
              int ntiles, int lognx)
{
    extern __shared__ __align__(128) char smem[];
    uint32_t sb;
    asm("{ .reg .u64 t; cvta.to.shared.u64 t, %1; cvt.u32.u64 %0, t; }" : "=r"(sb) : "l"(smem));

    const int tid  = threadIdx.x;
    const int warp = tid >> 5;
    const int lane = tid & 31;
    const int grp  = lane >> 2;
    const int tig  = lane & 3;
    const int wm   = (warp & 1) * 64;
    const int wn   = (warp >> 1) * 32;
    const int bx   = blockIdx.x;
    const int G    = gridDim.x;
    const int nxm1 = (1 << lognx) - 1;

    const int nloc = (ntiles - bx + G - 1) / G;   // local tile count (>=1 for our launches)
    const int total_slabs = nloc * NST;

    float acc[4][4][4];
    #pragma unroll
    for (int i = 0; i < 4; i++)
        #pragma unroll
        for (int j = 0; j < 4; j++)
            #pragma unroll
            for (int k = 0; k < 4; k++) acc[i][j][k] = 0.0f;

    // ldmatrix lane offsets (stage-relative; chunk c at +32B*c)
    const int lg  = lane >> 3;
    const int lr8 = lane & 7;
    uint32_t aoff[4];
    #pragma unroll
    for (int mi = 0; mi < 4; mi++)
        aoff[mi] = (uint32_t)((wm + mi * 16 + (lg & 1) * 8 + lr8) * SROW_B + (lg >> 1) * 16);
    uint32_t boff[2];
    #pragma unroll
    for (int jj = 0; jj < 2; jj++)
        boff[jj] = (uint32_t)((BM + wn + (jj * 2 + (lg >> 1)) * 8 + lr8) * SROW_B + (lg & 1) * 16);

    // sector-clean fill constants: fr0 = tid>>3 (0..31), fc = (tid&7)*16 bytes
    const int fr0 = tid >> 3;
    const int fc  = (tid & 7) * 16;
    const uint32_t aDbase = sb + fr0 * SROW_B + fc;
    const uint32_t bDbase = sb + (BM + fr0) * SROW_B + fc;

    // fill slab s (global local-slab index) into smem slot
    auto fill_slab = [&](int s, int slotIdx) {
        const int lt  = s >> 4;          // NST == 16
        const int ks  = s & 15;
        const int t   = bx + lt * G;
        const int r0  = (t >> lognx) * BM;
        const int c0  = (t & nxm1) * BN;
        const __half* Ag = A + (size_t)(r0 + fr0) * lda + ks * 64 + fc / 2;
        const __half* Wg = W + (size_t)(c0 + fr0) * E_DIM + ks * 64 + fc / 2;
        const uint32_t aD = aDbase + slotIdx * STAGE_B;
        const uint32_t bD = bDbase + slotIdx * STAGE_B;
        #pragma unroll
        for (int i = 0; i < 4; i++) {
            CP_ASYNC16(aD + i * 32 * SROW_B, Ag + (size_t)i * 32 * lda);
            CP_ASYNC16(bD + i * 32 * SROW_B, Wg + (size_t)i * 32 * E_DIM);
        }
    };

    // prologue: slabs 0,1 -> slots 0,1
    fill_slab(0, 0);
    asm volatile("cp.async.commit_group;\n");
    fill_slab(1, 1);
    asm volatile("cp.async.commit_group;\n");

    int slot = 0;
    for (int s = 0; s < total_slabs; s++) {
        asm volatile("cp.async.wait_group 1;\n");
        __syncthreads();

        if (s + 2 < total_slabs) {
            const int ps = (slot + 2 >= STAGES) ? slot + 2 - STAGES : slot + 2;
            fill_slab(s + 2, ps);
        }
        asm volatile("cp.async.commit_group;\n");

        const uint32_t stage = sb + slot * STAGE_B;

        uint32_t af[2][4][4], bf[2][4][2];
        #pragma unroll
        for (int mi = 0; mi < 4; mi++)
            LDSM_X4(af[0][mi][0], af[0][mi][1], af[0][mi][2], af[0][mi][3], stage + aoff[mi]);
        #pragma unroll
        for (int jj = 0; jj < 2; jj++)
            LDSM_X4(bf[0][jj * 2][0], bf[0][jj * 2][1],
                    bf[0][jj * 2 + 1][0], bf[0][jj * 2 + 1][1], stage + boff[jj]);

        #pragma unroll
        for (int c = 0; c < 4; c++) {
            const int cur = c & 1, nxt = cur ^ 1;
            if (c < 3) {
                const uint32_t co = (uint32_t)(c + 1) * 32;
                #pragma unroll
                for (int mi = 0; mi < 4; mi++)
                    LDSM_X4(af[nxt][mi][0], af[nxt][mi][1], af[nxt][mi][2], af[nxt][mi][3],
                            stage + aoff[mi] + co);
                #pragma unroll
                for (int jj = 0; jj < 2; jj++)
                    LDSM_X4(bf[nxt][jj * 2][0], bf[nxt][jj * 2][1],
                            bf[nxt][jj * 2 + 1][0], bf[nxt][jj * 2 + 1][1],
                            stage + boff[jj] + co);
            }
            #pragma unroll
            for (int mi = 0; mi < 4; mi++)
                #pragma unroll
                for (int ni = 0; ni < 4; ni++)
                    MMA16816(acc[mi][ni], af[cur][mi], bf[cur][ni]);
        }

        // tile finished -> epilogue (regs+gmem only; no smem, no extra sync)
        if ((s & 15) == 15) {
            const int t  = bx + (s >> 4) * G;
            const int r0 = (t >> lognx) * BM;
            const int c0 = (t & nxm1) * BN;
            #pragma unroll
            for (int ni = 0; ni < 4; ni++) {
                const int col = c0 + wn + ni * 8 + tig * 2;
                float bv0 = 0.0f, bv1 = 0.0f;
                if (bias) { bv0 = bias[col]; bv1 = bias[col + 1]; }
                #pragma unroll
                for (int mi = 0; mi < 4; mi++) {
                    #pragma unroll
                    for (int half_ = 0; half_ < 2; half_++) {
                        const int row = r0 + wm + mi * 16 + grp + half_ * 8;
                        float v0 = acc[mi][ni][half_ * 2 + 0] + bv0;
                        float v1 = acc[mi][ni][half_ * 2 + 1] + bv1;
                        if (ACT == 1) { v0 = gelu_exact(v0); v1 = gelu_exact(v1); }
                        if (OUTF) {
                            *(float2*)((float*)Cv + (size_t)row * ldc + col) = make_float2(v0, v1);
                        } else {
                            *(__half2*)((__half*)Cv + (size_t)row * ldc + col) =
                                __floats2half2_rn(v0, v1);
                        }
                        acc[mi][ni][half_ * 2 + 0] = 0.0f;
                        acc[mi][ni][half_ * 2 + 1] = 0.0f;
                    }
                }
            }
        }

        slot = (slot + 1 >= STAGES) ? 0 : slot + 1;
    }
}

// ---------------------------------------------------------------------------
// Batched in-place LayerNorm: 2 jobs (rows of 1024 halves, eps=1e-6)
// ---------------------------------------------------------------------------
__global__ void ln2_kernel(__half* __restrict__ d0, const float* __restrict__ w0,
                           const float* __restrict__ b0,
                           __half* __restrict__ d1, const float* __restrict__ w1,
                           const float* __restrict__ b1, int rows_per_job)
{
    const int job = blockIdx.x / rows_per_job;
    const int row = blockIdx.x - job * rows_per_job;
    __half* data = job ? d1 : d0;
    const float* w = job ? w1 : w0;
    const float* b = job ? b1 : b0;

    __half2* p = (__half2*)(data + (size_t)row * E_DIM);
    const __half2 h0 = p[2 * threadIdx.x], h1 = p[2 * threadIdx.x + 1];
    float2 f0 = __half22float2(h0), f1 = __half22float2(h1);
    float s = f0.x + f0.y + f1.x + f1.y;
    float q = f0.x * f0.x + f0.y * f0.y + f1.x * f1.x + f1.y * f1.y;
    #pragma unroll
    for (int o = 16; o; o >>= 1) {
        s += __shfl_xor_sync(0xffffffffu, s, o);
        q += __shfl_xor_sync(0xffffffffu, q, o);
    }
    __shared__ float ss[8], sq[8];
    const int warp = threadIdx.x >> 5, lane = threadIdx.x & 31;
    if (lane == 0) { ss[warp] = s; sq[warp] = q; }
    __syncthreads();
    if (warp == 0) {
        s = (lane < 8) ? ss[lane] : 0.0f;
        q = (lane < 8) ? sq[lane] : 0.0f;
        #pragma unroll
        for (int o = 4; o; o >>= 1) {
            s += __shfl_xor_sync(0xffffffffu, s, o);
            q += __shfl_xor_sync(0xffffffffu, q, o);
        }
        if (lane == 0) { ss[0] = s; sq[0] = q; }
    }
    __syncthreads();
    const float mean = ss[0] * (1.0f / 1024.0f);
    const float var  = sq[0] * (1.0f / 1024.0f) - mean * mean;
    const float rstd = rsqrtf(var + 1e-6f);
    const float4 wv = ((const float4*)w)[threadIdx.x];
    const float4 bv = ((const float4*)b)[threadIdx.x];
    p[2 * threadIdx.x] = __floats2half2_rn((f0.x - mean) * rstd * wv.x + bv.x,
                                           (f0.y - mean) * rstd * wv.y + bv.y);
    p[2 * threadIdx.x + 1] = __floats2half2_rn((f1.x - mean) * rstd * wv.z + bv.z,
                                               (f1.y - mean) * rstd * wv.w + bv.w);
}

// ---------------------------------------------------------------------------
// Attention: q len 1 over 2x2 key patch. fp16 in/out, fp32 math.
// ---------------------------------------------------------------------------
__global__ void attn_kernel(const __half* __restrict__ qh, const __half* __restrict__ kh,
                            const __half* __restrict__ vh, __half* __restrict__ o)
{
    const int r  = blockIdx.x;
    const int n  = r / NQ_TOK;
    const int qi = r - n * NQ_TOK;
    const int ar = qi / 12;
    const int ac = qi - ar * 12;
    const int head = threadIdx.x >> 5, lane = threadIdx.x & 31;
    const size_t qoff = (size_t)r * E_DIM + head * 128 + lane * 4;
    const __half2* qp = (const __half2*)(qh + qoff);
    const float2 q0 = __half22float2(qp[0]), q1 = __half22float2(qp[1]);

    int trow[4];
    #pragma unroll
    for (int j = 0; j < 4; j++)
        trow[j] = n * TN_TOK + (2 * ar + (j >> 1)) * 24 + (2 * ac + (j & 1));

    float s[4];
    #pragma unroll
    for (int j = 0; j < 4; j++) {
        const __half2* kp = (const __half2*)(kh + (size_t)trow[j] * E_DIM + head * 128 + lane * 4);
        const float2 k0 = __half22float2(kp[0]), k1 = __half22float2(kp[1]);
        float d = q0.x * k0.x + q0.y * k0.y + q1.x * k1.x + q1.y * k1.y;
        #pragma unroll
        for (int off = 16; off; off >>= 1) d += __shfl_xor_sync(0xffffffffu, d, off);
        s[j] = d * 0.08838834764831843f;
    }
    const float m = fmaxf(fmaxf(s[0], s[1]), fmaxf(s[2], s[3]));
    float e[4], tot = 0.0f;
    #pragma unroll
    for (int j = 0; j < 4; j++) { e[j] = expf(s[j] - m); tot += e[j]; }
    const float inv = 1.0f / tot;

    float a0 = 0.f, a1 = 0.f, a2 = 0.f, a3 = 0.f;
    #pragma unroll
    for (int j = 0; j < 4; j++) {
        const float pj = e[j] * inv;
        const __half2* vp = (const __half2*)(vh + (size_t)trow[j] * E_DIM + head * 128 + lane * 4);
        const float2 v0 = __half22float2(vp[0]), v1 = __half22float2(vp[1]);
        a0 += pj * v0.x; a1 += pj * v0.y; a2 += pj * v1.x; a3 += pj * v1.y;
    }
    __half2* op = (__half2*)(o + qoff);
    op[0] = __floats2half2_rn(a0, a1);
    op[1] = __floats2half2_rn(a2, a3);
}

// ---------------------------------------------------------------------------
extern "C" void kernel_launch(void* const* d_in, const int* in_sizes, int n_in,
                              void* d_out, int out_size)
{
    const float* x      = (const float*)d_in[0];
    const float* x_feat = (const float*)d_in[1];
    const float* w_q    = (const float*)d_in[2];
    const float* w_k1   = (const float*)d_in[3];
    const float* b_k1   = (const float*)d_in[4];
    const float* w_k2   = (const float*)d_in[5];
    const float* b_k2   = (const float*)d_in[6];
    const float* w_v1   = (const float*)d_in[7];
    const float* b_v1   = (const float*)d_in[8];
    const float* w_v2   = (const float*)d_in[9];
    const float* b_v2   = (const float*)d_in[10];
    const float* ln_q_w = (const float*)d_in[11];
    const float* ln_q_b = (const float*)d_in[12];
    const float* ln_k_w = (const float*)d_in[13];
    const float* ln_k_b = (const float*)d_in[14];
    const float* ln_v_w = (const float*)d_in[15];
    const float* ln_v_b = (const float*)d_in[16];
    const float* in_w   = (const float*)d_in[17];
    const float* in_b   = (const float*)d_in[18];
    const float* out_w  = (const float*)d_in[19];
    const float* out_b  = (const float*)d_in[20];

    __half *h2, *key, *val, *kh, *vh, *qb, *qh, *o, *xr, *xfr, *wt;
    float* bcat;
    cudaGetSymbolAddress((void**)&h2,  g_h2);
    cudaGetSymbolAddress((void**)&key, g_key);
    cudaGetSymbolAddress((void**)&val, g_val);
    cudaGetSymbolAddress((void**)&kh,  g_kh);
    cudaGetSymbolAddress((void**)&vh,  g_vh);
    cudaGetSymbolAddress((void**)&qb,  g_q);
    cudaGetSymbolAddress((void**)&qh,  g_qh);
    cudaGetSymbolAddress((void**)&o,   g_o);
    cudaGetSymbolAddress((void**)&xr,  g_xr);
    cudaGetSymbolAddress((void**)&xfr, g_xfr);
    cudaGetSymbolAddress((void**)&wt,  g_wt);
    cudaGetSymbolAddress((void**)&bcat, g_bcat);

    const size_t MW = 1024ull * 1024ull;
    __half* wt_kv1 = wt;                 // [w_k1 ; w_v1]
    __half* wt_k2  = wt + 2 * MW;
    __half* wt_v2  = wt + 3 * MW;
    __half* wt_q   = wt + 4 * MW;
    __half* wt_in  = wt + 5 * MW;        // 3 MW
    __half* wt_out = wt + 8 * MW;

    const int smem_bytes = STAGES * STAGE_B;  // 110592
    cudaFuncSetAttribute(gemm_f16<0, 0>, cudaFuncAttributeMaxDynamicSharedMemorySize, smem_bytes);
    cudaFuncSetAttribute(gemm_f16<1, 0>, cudaFuncAttributeMaxDynamicSharedMemorySize, smem_bytes);
    cudaFuncSetAttribute(gemm_f16<0, 1>, cudaFuncAttributeMaxDynamicSharedMemorySize, smem_bytes);

    // launch 1: merged conversion prepass
    {
        ConvJobs jobs;
        jobs.j[0] = { (const float4*)x,      (__half2*)xr,      M_SMALL * E_DIM / 4 };
        jobs.j[1] = { (const float4*)x_feat, (__half2*)xfr,     M_BIG   * E_DIM / 4 };
        jobs.j[2] = { (const float4*)w_k1,   (__half2*)wt_kv1,  (int)(MW / 4) };
        jobs.j[3] = { (const float4*)w_v1,   (__half2*)(wt_kv1 + MW), (int)(MW / 4) };
        jobs.j[4] = { (const float4*)w_k2,   (__half2*)wt_k2,   (int)(MW / 4) };
        jobs.j[5] = { (const float4*)w_v2,   (__half2*)wt_v2,   (int)(MW / 4) };
        jobs.j[6] = { (const float4*)w_q,    (__half2*)wt_q,    (int)(MW / 4) };
        jobs.j[7] = { (const float4*)in_w,   (__half2*)wt_in,   (int)(3 * MW / 4) };
        jobs.j[8] = { (const float4*)out_w,  (__half2*)wt_out,  (int)(MW / 4) };
        conv_all_kernel<<<dim3(1024, 9), 256>>>(jobs);
    }
    // launch 2: bias concat
    bias_concat_kernel<<<8, 256>>>(b_k1, b_v1, bcat);

    const dim3 blk(256);
    const int TKV = (M_BIG / BM) * 16;   // 4608 tiles, lognx=4
    const int TBG = (M_BIG / BM) * 8;    // 2304 tiles, lognx=3
    const int TSM = (M_SMALL / BM) * 8;  // 576 tiles,  lognx=3

    // launch 3: merged K1+V1 (gelu) -> h2 [M_BIG x 2048]
    gemm_f16<1, 0><<<PGRID, blk, smem_bytes>>>(xfr, E_DIM, wt_kv1, bcat, h2, 2048, TKV, 4);
    // launch 4 (ncu capture slot): K2
    gemm_f16<0, 0><<<PGRID, blk, smem_bytes>>>(h2, 2048, wt_k2, b_k2, key, E_DIM, TBG, 3);
    // launch 5: V2
    gemm_f16<0, 0><<<PGRID, blk, smem_bytes>>>(h2 + 1024, 2048, wt_v2, b_v2, val, E_DIM, TBG, 3);
    // batched LN over key+val
    ln2_kernel<<<2 * M_BIG, 256>>>(key, ln_k_w, ln_k_b, val, ln_v_w, ln_v_b, M_BIG);
    // Q path
    gemm_f16<0, 0><<<PGRID, blk, smem_bytes>>>(xr, E_DIM, wt_q, nullptr, qb, E_DIM, TSM, 3);
    ln2_kernel<<<M_SMALL, 256>>>(qb, ln_q_w, ln_q_b, qb, ln_q_w, ln_q_b, M_SMALL);
    // in_proj
    gemm_f16<0, 0><<<PGRID, blk, smem_bytes>>>(qb,  E_DIM, wt_in,          in_b,        qh, E_DIM, TSM, 3);
    gemm_f16<0, 0><<<PGRID, blk, smem_bytes>>>(key, E_DIM, wt_in + MW,     in_b + 1024, kh, E_DIM, TBG, 3);
    gemm_f16<0, 0><<<PGRID, blk, smem_bytes>>>(val, E_DIM, wt_in + 2 * MW, in_b + 2048, vh, E_DIM, TBG, 3);
    // attention
    attn_kernel<<<M_SMALL, 256>>>(qh, kh, vh, o);
    // out_proj -> d_out (float)
    gemm_f16<0, 1><<<PGRID, blk, smem_bytes>>>(o, E_DIM, wt_out, out_b, d_out, E_DIM, TSM, 3);
}

// round 13
// speedup vs baseline: 1.0600x; 1.0600x over previous
#include <cuda_runtime.h>
#include <cuda_fp16.h>
#include <cstdint>
#include <math.h>

// ---------------------------------------------------------------------------
// TokenPacker R13: R11 GEMM core (K=64 stages, 3-deep cp.async, sector-clean
// fill, chunk double-buffer) + chunk0-LDSM-before-fill reorder + dual-job
// (blockIdx.z) merged launches for K2+V2 and kh+vh + wider conv grid.
// R12 post-mortem: persistent CTAs added hot-loop index ALU (+4% ALU) and
// lost L2 tile locality -> reverted.
// ---------------------------------------------------------------------------

#define E_DIM   1024
#define N_IMG   64
#define NQ_TOK  144
#define TN_TOK  576
#define M_BIG   (N_IMG * TN_TOK)   // 36864
#define M_SMALL (N_IMG * NQ_TOK)   // 9216
#define NST     16                 // K / 64 stages
#define STAGES  3
#define SROW_B  144                // pitch bytes (128B payload + 16 pad)
#define BM      128
#define BN      128
#define STAGE_B ((BM + BN) * SROW_B)   // 36864
#define MW      (1024 * 1024)

// Scratch (device statics; no cudaMalloc allowed)
__device__ __align__(256) __half g_h2 [(size_t)M_BIG * 2048];   // gelu(K1|V1)
__device__ __align__(256) __half g_key[(size_t)M_BIG   * E_DIM];
__device__ __align__(256) __half g_val[(size_t)M_BIG   * E_DIM];
__device__ __align__(256) __half g_kh [(size_t)M_BIG   * E_DIM];
__device__ __align__(256) __half g_vh [(size_t)M_BIG   * E_DIM];
__device__ __align__(256) __half g_q  [(size_t)M_SMALL * E_DIM];
__device__ __align__(256) __half g_qh [(size_t)M_SMALL * E_DIM];
__device__ __align__(256) __half g_o  [(size_t)M_SMALL * E_DIM];
__device__ __align__(256) __half g_xr [(size_t)M_SMALL * E_DIM];
__device__ __align__(256) __half g_xfr[(size_t)M_BIG   * E_DIM];
__device__ __align__(256) __half g_wt [9ull * 1024 * 1024];
__device__ __align__(256) float  g_bcat[2048];

__device__ __forceinline__ float gelu_exact(float x) {
    return 0.5f * x * (1.0f + erff(x * 0.70710678118654752f));
}

#define CP_ASYNC16(smem_u32a, gptr) \
    asm volatile("cp.async.cg.shared.global [%0], [%1], 16;\n" :: "r"(smem_u32a), "l"(gptr))

#define LDSM_X4(r0, r1, r2, r3, addr) \
    asm volatile("ldmatrix.sync.aligned.m8n8.x4.shared.b16 {%0,%1,%2,%3}, [%4];" \
                 : "=r"(r0), "=r"(r1), "=r"(r2), "=r"(r3) : "r"(addr))

#define MMA16816(d, a, b) \
    asm volatile("mma.sync.aligned.m16n8k16.row.col.f32.f16.f16.f32 " \
                 "{%0,%1,%2,%3}, {%4,%5,%6,%7}, {%8,%9}, {%0,%1,%2,%3};\n" \
                 : "+f"((d)[0]), "+f"((d)[1]), "+f"((d)[2]), "+f"((d)[3]) \
                 : "r"((a)[0]), "r"((a)[1]), "r"((a)[2]), "r"((a)[3]), \
                   "r"((b)[0]), "r"((b)[1]))

// ---------------------------------------------------------------------------
// Merged f32 -> f16 conversion prepass
// ---------------------------------------------------------------------------
struct ConvJob { const float4* src; __half2* dst; int n4; };
struct ConvJobs { ConvJob j[9]; };

__global__ void conv_all_kernel(ConvJobs jobs)
{
    const ConvJob jb = jobs.j[blockIdx.y];
    for (int i = blockIdx.x * blockDim.x + threadIdx.x; i < jb.n4;
         i += gridDim.x * blockDim.x) {
        float4 v = jb.src[i];
        jb.dst[2 * i]     = __floats2half2_rn(v.x, v.y);
        jb.dst[2 * i + 1] = __floats2half2_rn(v.z, v.w);
    }
}

__global__ void bias_concat_kernel(const float* __restrict__ b0,
                                   const float* __restrict__ b1,
                                   float* __restrict__ out)
{
    int i = blockIdx.x * blockDim.x + threadIdx.x;
    out[i] = (i < 1024) ? b0[i] : b1[i - 1024];
}

// ---------------------------------------------------------------------------
// GEMM (dual-job): job z = blockIdx.z selects {A, W = W0 + z*MW, bias, C}.
// C[M x N] = act(A[M x K=1024] @ W[N x 1024]^T + bias)
// K=64 stages, 3-deep pipeline, sector-clean fill, chunk double-buffer,
// chunk0 LDSM issued before the stage fill (shadow reduction).
// ---------------------------------------------------------------------------
template <int ACT, int OUTF>
__global__ __launch_bounds__(256, 2)
void gemm_f16(const __half* __restrict__ A0, const __half* __restrict__ A1, int lda,
              const __half* __restrict__ W0,
              const float* __restrict__ bias0, const float* __restrict__ bias1,
              void* __restrict__ C0, void* __restrict__ C1, int ldc)
{
    extern __shared__ __align__(128) char smem[];
    uint32_t sb;
    asm("{ .reg .u64 t; cvta.to.shared.u64 t, %1; cvt.u32.u64 %0, t; }" : "=r"(sb) : "l"(smem));

    const int z = blockIdx.z;
    const __half* A   = z ? A1 : A0;
    const __half* W   = W0 + (size_t)z * MW;
    const float* bias = z ? bias1 : bias0;
    void* Cv          = z ? C1 : C0;

    const int tid  = threadIdx.x;
    const int warp = tid >> 5;
    const int lane = tid & 31;
    const int grp  = lane >> 2;
    const int tig  = lane & 3;
    const int wm   = (warp & 1) * 64;
    const int wn   = (warp >> 1) * 32;
    const int row0 = blockIdx.y * BM;
    const int col0 = blockIdx.x * BN;

    float acc[4][4][4];
    #pragma unroll
    for (int i = 0; i < 4; i++)
        #pragma unroll
        for (int j = 0; j < 4; j++)
            #pragma unroll
            for (int k = 0; k < 4; k++) acc[i][j][k] = 0.0f;

    // ldmatrix lane offsets (chunk c at +32B * c)
    const int lg  = lane >> 3;
    const int lr8 = lane & 7;
    uint32_t aoff[4];
    #pragma unroll
    for (int mi = 0; mi < 4; mi++)
        aoff[mi] = (uint32_t)((wm + mi * 16 + (lg & 1) * 8 + lr8) * SROW_B + (lg >> 1) * 16);
    uint32_t boff[2];
    #pragma unroll
    for (int jj = 0; jj < 2; jj++)
        boff[jj] = (uint32_t)((BM + wn + (jj * 2 + (lg >> 1)) * 8 + lr8) * SROW_B + (lg & 1) * 16);

    // sector-clean fill: 8 lanes x 16B = 128B contiguous per row.
    const int fr0 = tid >> 3;
    const int fc  = (tid & 7) * 16;   // bytes
    const __half* Ag = A + (size_t)(row0 + fr0) * lda + fc / 2;
    const __half* Wg = W + (size_t)(col0 + fr0) * E_DIM + fc / 2;
    const uint32_t aD = sb + fr0 * SROW_B + fc;
    const uint32_t bD = sb + (BM + fr0) * SROW_B + fc;

    #pragma unroll
    for (int st = 0; st < 2; st++) {
        const int ko = st * 64;   // halves
        #pragma unroll
        for (int i = 0; i < 4; i++) {
            CP_ASYNC16(aD + st * STAGE_B + i * 32 * SROW_B, Ag + (size_t)i * 32 * lda + ko);
            CP_ASYNC16(bD + st * STAGE_B + i * 32 * SROW_B, Wg + (size_t)i * 32 * E_DIM + ko);
        }
        asm volatile("cp.async.commit_group;\n");
    }

    int slot = 0;
    for (int it = 0; it < NST; it++) {
        asm volatile("cp.async.wait_group 1;\n");
        __syncthreads();

        const uint32_t stage = sb + slot * STAGE_B;

        // chunk0 fragments FIRST (their latency runs under the fill issue below)
        uint32_t af[2][4][4], bf[2][4][2];
        #pragma unroll
        for (int mi = 0; mi < 4; mi++)
            LDSM_X4(af[0][mi][0], af[0][mi][1], af[0][mi][2], af[0][mi][3], stage + aoff[mi]);
        #pragma unroll
        for (int jj = 0; jj < 2; jj++)
            LDSM_X4(bf[0][jj * 2][0], bf[0][jj * 2][1],
                    bf[0][jj * 2 + 1][0], bf[0][jj * 2 + 1][1], stage + boff[jj]);

        // stage fill (target slot differs from both the read slot and slot+1)
        const int pf = it + 2;
        if (pf < NST) {
            const int s = (slot + 2 >= STAGES) ? slot + 2 - STAGES : slot + 2;
            const int ko = pf * 64;
            #pragma unroll
            for (int i = 0; i < 4; i++) {
                CP_ASYNC16(aD + s * STAGE_B + i * 32 * SROW_B, Ag + (size_t)i * 32 * lda + ko);
                CP_ASYNC16(bD + s * STAGE_B + i * 32 * SROW_B, Wg + (size_t)i * 32 * E_DIM + ko);
            }
        }
        asm volatile("cp.async.commit_group;\n");

        #pragma unroll
        for (int c = 0; c < 4; c++) {
            const int cur = c & 1, nxt = cur ^ 1;
            if (c < 3) {
                const uint32_t co = (uint32_t)(c + 1) * 32;
                #pragma unroll
                for (int mi = 0; mi < 4; mi++)
                    LDSM_X4(af[nxt][mi][0], af[nxt][mi][1], af[nxt][mi][2], af[nxt][mi][3],
                            stage + aoff[mi] + co);
                #pragma unroll
                for (int jj = 0; jj < 2; jj++)
                    LDSM_X4(bf[nxt][jj * 2][0], bf[nxt][jj * 2][1],
                            bf[nxt][jj * 2 + 1][0], bf[nxt][jj * 2 + 1][1],
                            stage + boff[jj] + co);
            }
            #pragma unroll
            for (int mi = 0; mi < 4; mi++)
                #pragma unroll
                for (int ni = 0; ni < 4; ni++)
                    MMA16816(acc[mi][ni], af[cur][mi], bf[cur][ni]);
        }

        slot = (slot + 1 >= STAGES) ? 0 : slot + 1;
    }

    // epilogue
    #pragma unroll
    for (int ni = 0; ni < 4; ni++) {
        const int col = col0 + wn + ni * 8 + tig * 2;
        float bv0 = 0.0f, bv1 = 0.0f;
        if (bias) { bv0 = bias[col]; bv1 = bias[col + 1]; }
        #pragma unroll
        for (int mi = 0; mi < 4; mi++) {
            #pragma unroll
            for (int half_ = 0; half_ < 2; half_++) {
                const int row = row0 + wm + mi * 16 + grp + half_ * 8;
                float v0 = acc[mi][ni][half_ * 2 + 0] + bv0;
                float v1 = acc[mi][ni][half_ * 2 + 1] + bv1;
                if (ACT == 1) { v0 = gelu_exact(v0); v1 = gelu_exact(v1); }
                if (OUTF) {
                    *(float2*)((float*)Cv + (size_t)row * ldc + col) = make_float2(v0, v1);
                } else {
                    *(__half2*)((__half*)Cv + (size_t)row * ldc + col) = __floats2half2_rn(v0, v1);
                }
            }
        }
    }
}

// ---------------------------------------------------------------------------
// Batched in-place LayerNorm: 2 jobs (rows of 1024 halves, eps=1e-6)
// ---------------------------------------------------------------------------
__global__ void ln2_kernel(__half* __restrict__ d0, const float* __restrict__ w0,
                           const float* __restrict__ b0,
                           __half* __restrict__ d1, const float* __restrict__ w1,
                           const float* __restrict__ b1, int rows_per_job)
{
    const int job = blockIdx.x / rows_per_job;
    const int row = blockIdx.x - job * rows_per_job;
    __half* data = job ? d1 : d0;
    const float* w = job ? w1 : w0;
    const float* b = job ? b1 : b0;

    __half2* p = (__half2*)(data + (size_t)row * E_DIM);
    const __half2 h0 = p[2 * threadIdx.x], h1 = p[2 * threadIdx.x + 1];
    float2 f0 = __half22float2(h0), f1 = __half22float2(h1);
    float s = f0.x + f0.y + f1.x + f1.y;
    float q = f0.x * f0.x + f0.y * f0.y + f1.x * f1.x + f1.y * f1.y;
    #pragma unroll
    for (int o = 16; o; o >>= 1) {
        s += __shfl_xor_sync(0xffffffffu, s, o);
        q += __shfl_xor_sync(0xffffffffu, q, o);
    }
    __shared__ float ss[8], sq[8];
    const int warp = threadIdx.x >> 5, lane = threadIdx.x & 31;
    if (lane == 0) { ss[warp] = s; sq[warp] = q; }
    __syncthreads();
    if (warp == 0) {
        s = (lane < 8) ? ss[lane] : 0.0f;
        q = (lane < 8) ? sq[lane] : 0.0f;
        #pragma unroll
        for (int o = 4; o; o >>= 1) {
            s += __shfl_xor_sync(0xffffffffu, s, o);
            q += __shfl_xor_sync(0xffffffffu, q, o);
        }
        if (lane == 0) { ss[0] = s; sq[0] = q; }
    }
    __syncthreads();
    const float mean = ss[0] * (1.0f / 1024.0f);
    const float var  = sq[0] * (1.0f / 1024.0f) - mean * mean;
    const float rstd = rsqrtf(var + 1e-6f);
    const float4 wv = ((const float4*)w)[threadIdx.x];
    const float4 bv = ((const float4*)b)[threadIdx.x];
    p[2 * threadIdx.x] = __floats2half2_rn((f0.x - mean) * rstd * wv.x + bv.x,
                                           (f0.y - mean) * rstd * wv.y + bv.y);
    p[2 * threadIdx.x + 1] = __floats2half2_rn((f1.x - mean) * rstd * wv.z + bv.z,
                                               (f1.y - mean) * rstd * wv.w + bv.w);
}

// ---------------------------------------------------------------------------
// Attention: q len 1 over 2x2 key patch. fp16 in/out, fp32 math.
// ---------------------------------------------------------------------------
__global__ void attn_kernel(const __half* __restrict__ qh, const __half* __restrict__ kh,
                            const __half* __restrict__ vh, __half* __restrict__ o)
{
    const int r  = blockIdx.x;
    const int n  = r / NQ_TOK;
    const int qi = r - n * NQ_TOK;
    const int ar = qi / 12;
    const int ac = qi - ar * 12;
    const int head = threadIdx.x >> 5, lane = threadIdx.x & 31;
    const size_t qoff = (size_t)r * E_DIM + head * 128 + lane * 4;
    const __half2* qp = (const __half2*)(qh + qoff);
    const float2 q0 = __half22float2(qp[0]), q1 = __half22float2(qp[1]);

    int trow[4];
    #pragma unroll
    for (int j = 0; j < 4; j++)
        trow[j] = n * TN_TOK + (2 * ar + (j >> 1)) * 24 + (2 * ac + (j & 1));

    float s[4];
    #pragma unroll
    for (int j = 0; j < 4; j++) {
        const __half2* kp = (const __half2*)(kh + (size_t)trow[j] * E_DIM + head * 128 + lane * 4);
        const float2 k0 = __half22float2(kp[0]), k1 = __half22float2(kp[1]);
        float d = q0.x * k0.x + q0.y * k0.y + q1.x * k1.x + q1.y * k1.y;
        #pragma unroll
        for (int off = 16; off; off >>= 1) d += __shfl_xor_sync(0xffffffffu, d, off);
        s[j] = d * 0.08838834764831843f;
    }
    const float m = fmaxf(fmaxf(s[0], s[1]), fmaxf(s[2], s[3]));
    float e[4], tot = 0.0f;
    #pragma unroll
    for (int j = 0; j < 4; j++) { e[j] = expf(s[j] - m); tot += e[j]; }
    const float inv = 1.0f / tot;

    float a0 = 0.f, a1 = 0.f, a2 = 0.f, a3 = 0.f;
    #pragma unroll
    for (int j = 0; j < 4; j++) {
        const float pj = e[j] * inv;
        const __half2* vp = (const __half2*)(vh + (size_t)trow[j] * E_DIM + head * 128 + lane * 4);
        const float2 v0 = __half22float2(vp[0]), v1 = __half22float2(vp[1]);
        a0 += pj * v0.x; a1 += pj * v0.y; a2 += pj * v1.x; a3 += pj * v1.y;
    }
    __half2* op = (__half2*)(o + qoff);
    op[0] = __floats2half2_rn(a0, a1);
    op[1] = __floats2half2_rn(a2, a3);
}

// ---------------------------------------------------------------------------
extern "C" void kernel_launch(void* const* d_in, const int* in_sizes, int n_in,
                              void* d_out, int out_size)
{
    const float* x      = (const float*)d_in[0];
    const float* x_feat = (const float*)d_in[1];
    const float* w_q    = (const float*)d_in[2];
    const float* w_k1   = (const float*)d_in[3];
    const float* b_k1   = (const float*)d_in[4];
    const float* w_k2   = (const float*)d_in[5];
    const float* b_k2   = (const float*)d_in[6];
    const float* w_v1   = (const float*)d_in[7];
    const float* b_v1   = (const float*)d_in[8];
    const float* w_v2   = (const float*)d_in[9];
    const float* b_v2   = (const float*)d_in[10];
    const float* ln_q_w = (const float*)d_in[11];
    const float* ln_q_b = (const float*)d_in[12];
    const float* ln_k_w = (const float*)d_in[13];
    const float* ln_k_b = (const float*)d_in[14];
    const float* ln_v_w = (const float*)d_in[15];
    const float* ln_v_b = (const float*)d_in[16];
    const float* in_w   = (const float*)d_in[17];
    const float* in_b   = (const float*)d_in[18];
    const float* out_w  = (const float*)d_in[19];
    const float* out_b  = (const float*)d_in[20];

    __half *h2, *key, *val, *kh, *vh, *qb, *qh, *o, *xr, *xfr, *wt;
    float* bcat;
    cudaGetSymbolAddress((void**)&h2,  g_h2);
    cudaGetSymbolAddress((void**)&key, g_key);
    cudaGetSymbolAddress((void**)&val, g_val);
    cudaGetSymbolAddress((void**)&kh,  g_kh);
    cudaGetSymbolAddress((void**)&vh,  g_vh);
    cudaGetSymbolAddress((void**)&qb,  g_q);
    cudaGetSymbolAddress((void**)&qh,  g_qh);
    cudaGetSymbolAddress((void**)&o,   g_o);
    cudaGetSymbolAddress((void**)&xr,  g_xr);
    cudaGetSymbolAddress((void**)&xfr, g_xfr);
    cudaGetSymbolAddress((void**)&wt,  g_wt);
    cudaGetSymbolAddress((void**)&bcat, g_bcat);

    __half* wt_kv1 = wt;                 // [w_k1 ; w_v1]
    __half* wt_k2  = wt + 2 * (size_t)MW;   // wt_v2 = wt_k2 + MW (contiguous, dual-z)
    __half* wt_q   = wt + 4 * (size_t)MW;
    __half* wt_in  = wt + 5 * (size_t)MW;   // wqh | wkh | wvh (3 MW, contiguous)
    __half* wt_out = wt + 8 * (size_t)MW;

    const int smem_bytes = STAGES * STAGE_B;  // 110592
    cudaFuncSetAttribute(gemm_f16<0, 0>, cudaFuncAttributeMaxDynamicSharedMemorySize, smem_bytes);
    cudaFuncSetAttribute(gemm_f16<1, 0>, cudaFuncAttributeMaxDynamicSharedMemorySize, smem_bytes);
    cudaFuncSetAttribute(gemm_f16<0, 1>, cudaFuncAttributeMaxDynamicSharedMemorySize, smem_bytes);

    // launch 1: merged conversion prepass
    {
        ConvJobs jobs;
        jobs.j[0] = { (const float4*)x,      (__half2*)xr,      M_SMALL * E_DIM / 4 };
        jobs.j[1] = { (const float4*)x_feat, (__half2*)xfr,     M_BIG   * E_DIM / 4 };
        jobs.j[2] = { (const float4*)w_k1,   (__half2*)wt_kv1,  MW / 4 };
        jobs.j[3] = { (const float4*)w_v1,   (__half2*)(wt_kv1 + MW), MW / 4 };
        jobs.j[4] = { (const float4*)w_k2,   (__half2*)wt_k2,   MW / 4 };
        jobs.j[5] = { (const float4*)w_v2,   (__half2*)(wt_k2 + MW), MW / 4 };
        jobs.j[6] = { (const float4*)w_q,    (__half2*)wt_q,    MW / 4 };
        jobs.j[7] = { (const float4*)in_w,   (__half2*)wt_in,   3 * MW / 4 };
        jobs.j[8] = { (const float4*)out_w,  (__half2*)wt_out,  MW / 4 };
        conv_all_kernel<<<dim3(4096, 9), 256>>>(jobs);
    }
    // launch 2: bias concat
    bias_concat_kernel<<<8, 256>>>(b_k1, b_v1, bcat);

    const dim3 blk(256);
    const dim3 gKV(16, M_BIG / BM, 1);      // KV1: N=2048
    const dim3 gBig2(8, M_BIG / BM, 2);     // dual big GEMM
    const dim3 gSm(8, M_SMALL / BM, 1);

    // launch 3: merged K1+V1 (gelu) -> h2 [M_BIG x 2048]
    gemm_f16<1, 0><<<gKV, blk, smem_bytes>>>(xfr, xfr, E_DIM, wt_kv1, bcat, bcat, h2, h2, 2048);
    // launch 4 (ncu capture slot): K2 (z=0) + V2 (z=1) merged
    gemm_f16<0, 0><<<gBig2, blk, smem_bytes>>>(h2, h2 + 1024, 2048, wt_k2,
                                               b_k2, b_v2, key, val, E_DIM);
    // launch 5: batched LN over key+val
    ln2_kernel<<<2 * M_BIG, 256>>>(key, ln_k_w, ln_k_b, val, ln_v_w, ln_v_b, M_BIG);
    // Q path
    gemm_f16<0, 0><<<gSm, blk, smem_bytes>>>(xr, xr, E_DIM, wt_q, nullptr, nullptr, qb, qb, E_DIM);
    ln2_kernel<<<M_SMALL, 256>>>(qb, ln_q_w, ln_q_b, qb, ln_q_w, ln_q_b, M_SMALL);
    // in_proj: qh (small), then kh (z=0) + vh (z=1) merged (W = wt_in+MW, +2MW)
    gemm_f16<0, 0><<<gSm, blk, smem_bytes>>>(qb, qb, E_DIM, wt_in, in_b, in_b, qh, qh, E_DIM);
    gemm_f16<0, 0><<<gBig2, blk, smem_bytes>>>(key, val, E_DIM, wt_in + MW,
                                               in_b + 1024, in_b + 2048, kh, vh, E_DIM);
    // attention
    attn_kernel<<<M_SMALL, 256>>>(qh, kh, vh, o);
    // out_proj -> d_out (float)
    gemm_f16<0, 1><<<gSm, blk, smem_bytes>>>(o, o, E_DIM, wt_out, out_b, out_b,
                                             d_out, d_out, E_DIM);
}